// round 1
// baseline (speedup 1.0000x reference)
#include <cuda_runtime.h>
#include <math.h>
#include <stdint.h>

#define L_TOT  65536
#define HDIM   256
#define WDIM   256
#define DIM    192
#define C1     48
#define HMID   96
#define NTOK   8
#define KTOT   432   // 48*9

// ---------------- scratch (static device allocations) ----------------
__device__ float g_intensity[L_TOT];
__device__ float g_f1[C1 * L_TOT];            // conv1 output, channel-major [c][l]
__device__ float g_feat[(size_t)L_TOT * DIM]; // conv2 output, token-major  [l][c]
__device__ float g_gamma[L_TOT];
__device__ float g_beta[L_TOT];

// ---------------- K1: intensity ----------------
__global__ void k_intensity(const float* __restrict__ x) {
    int l = blockIdx.x * 256 + threadIdx.x;
    const float* p = x + (size_t)l * DIM;
    g_intensity[l] = 0.299f * p[0] + 0.587f * p[1] + 0.114f * p[2];
}

// ---------------- K2: conv1 1->48, 3x3 SAME, LeakyReLU(0.2) ----------------
__global__ void k_conv1(const float* __restrict__ w, const float* __restrict__ b) {
    int l  = blockIdx.x * 256 + threadIdx.x;
    int oc = blockIdx.y;
    int y = l >> 8, xx = l & 255;
    float acc = b[oc];
    #pragma unroll
    for (int ky = 0; ky < 3; ky++) {
        int gy = y + ky - 1;
        if (gy < 0 || gy >= HDIM) continue;
        #pragma unroll
        for (int kx = 0; kx < 3; kx++) {
            int gx = xx + kx - 1;
            if (gx < 0 || gx >= WDIM) continue;
            acc += w[oc * 9 + ky * 3 + kx] * g_intensity[(gy << 8) + gx];
        }
    }
    acc = (acc > 0.f) ? acc : 0.2f * acc;
    g_f1[oc * L_TOT + l] = acc;
}

// ---------------- K3: conv2 48->192, 3x3 SAME (tiled implicit GEMM) ----------------
// Tile: 64 oc x 64 pixels. 64 | 256 so a pixel tile lies in one image row.
// Per input channel: stage weights [9][64] and shifted pixels [9][64] in smem,
// thread computes a 4(pix) x 4(oc) register tile via float4 smem loads.
__global__ __launch_bounds__(256) void k_conv2(const float* __restrict__ w2,
                                               const float* __restrict__ b2) {
    __shared__ float Ws[9][68];
    __shared__ float Ps[9][68];
    int tid = threadIdx.x;
    int oc0 = (blockIdx.x % 3) * 64;
    int p0  = (blockIdx.x / 3) * 64;
    int y  = p0 >> 8;
    int x0 = p0 & 255;
    int tx = tid & 15;   // oc quad: oc0 + tx*4 + j
    int ty = tid >> 4;   // pix quad: p0 + ty*4 + i

    float acc[4][4];
    #pragma unroll
    for (int i = 0; i < 4; i++)
        #pragma unroll
        for (int j = 0; j < 4; j++) acc[i][j] = 0.f;

    for (int ic = 0; ic < C1; ic++) {
        // stage weights: Ws[kp][ocl]
        for (int idx = tid; idx < 576; idx += 256) {
            int ocl = idx / 9, kp = idx - ocl * 9;
            Ws[kp][ocl] = w2[(size_t)(oc0 + ocl) * KTOT + ic * 9 + kp];
        }
        // stage shifted pixel rows: Ps[kp][p]
        for (int idx = tid; idx < 576; idx += 256) {
            int kp = idx >> 6, p = idx & 63;
            int ky = kp / 3, kx = kp - ky * 3;
            int gy = y + ky - 1, gx = x0 + p + kx - 1;
            float v = 0.f;
            if (gy >= 0 && gy < HDIM && gx >= 0 && gx < WDIM)
                v = g_f1[ic * L_TOT + (gy << 8) + gx];
            Ps[kp][p] = v;
        }
        __syncthreads();
        #pragma unroll
        for (int kp = 0; kp < 9; kp++) {
            float4 a = *(const float4*)&Ps[kp][ty * 4];
            float4 b = *(const float4*)&Ws[kp][tx * 4];
            float av[4] = {a.x, a.y, a.z, a.w};
            float bv[4] = {b.x, b.y, b.z, b.w};
            #pragma unroll
            for (int i = 0; i < 4; i++)
                #pragma unroll
                for (int j = 0; j < 4; j++)
                    acc[i][j] += av[i] * bv[j];
        }
        __syncthreads();
    }
    float bj0 = b2[oc0 + tx * 4 + 0];
    float bj1 = b2[oc0 + tx * 4 + 1];
    float bj2 = b2[oc0 + tx * 4 + 2];
    float bj3 = b2[oc0 + tx * 4 + 3];
    #pragma unroll
    for (int i = 0; i < 4; i++) {
        int l = p0 + ty * 4 + i;
        float4 o = make_float4(acc[i][0] + bj0, acc[i][1] + bj1,
                               acc[i][2] + bj2, acc[i][3] + bj3);
        *(float4*)&g_feat[(size_t)l * DIM + oc0 + tx * 4] = o;
    }
}

// ---------------- K4: routing MLP + softmax + gumbel argmax -> gamma/beta --------
// 64 tokens per block. hmid GEMM (64x96, k=192) with k-chunked staging,
// then route2 (96->8), softmax, gumbel-perturbed argmax.
__global__ __launch_bounds__(256) void k_route(const float* __restrict__ x,
                                               const float* __restrict__ w1,
                                               const float* __restrict__ b1,
                                               const float* __restrict__ w2,
                                               const float* __restrict__ b2r,
                                               const float* __restrict__ gumbel,
                                               const float* __restrict__ emb) {
    __shared__ float z_s[64][17];
    __shared__ float W1s[16][97];
    __shared__ float hm_s[64][97];
    __shared__ float W2s[8][96];
    __shared__ float lg_s[64][9];
    int tid = threadIdx.x;
    int t0base = blockIdx.x * 64;
    int tx = tid & 15;   // hmid group: tx*6 + jj
    int ty = tid >> 4;   // tok group:  ty*4 + i

    for (int idx = tid; idx < 768; idx += 256)
        W2s[idx / 96][idx % 96] = w2[idx];

    float acc[4][6];
    #pragma unroll
    for (int i = 0; i < 4; i++)
        #pragma unroll
        for (int jj = 0; jj < 6; jj++) acc[i][jj] = 0.f;

    for (int k0 = 0; k0 < DIM; k0 += 16) {
        __syncthreads();
        for (int idx = tid; idx < 1024; idx += 256) {
            int tok = idx >> 4, kk = idx & 15;
            size_t off = (size_t)(t0base + tok) * DIM + k0 + kk;
            z_s[tok][kk] = x[off] + 0.3f * g_feat[off];
        }
        for (int idx = tid; idx < 1536; idx += 256) {
            int j = idx >> 4, kk = idx & 15;
            W1s[kk][j] = w1[j * DIM + k0 + kk];
        }
        __syncthreads();
        #pragma unroll
        for (int kk = 0; kk < 16; kk++) {
            float a[4], b[6];
            #pragma unroll
            for (int i = 0; i < 4; i++) a[i] = z_s[ty * 4 + i][kk];
            #pragma unroll
            for (int jj = 0; jj < 6; jj++) b[jj] = W1s[kk][tx * 6 + jj];
            #pragma unroll
            for (int i = 0; i < 4; i++)
                #pragma unroll
                for (int jj = 0; jj < 6; jj++) acc[i][jj] += a[i] * b[jj];
        }
    }
    __syncthreads();
    #pragma unroll
    for (int jj = 0; jj < 6; jj++) {
        float bb = b1[tx * 6 + jj];
        #pragma unroll
        for (int i = 0; i < 4; i++) {
            float v = acc[i][jj] + bb;
            v = 0.5f * v * (1.0f + erff(v * 0.7071067811865476f));  // exact GELU
            hm_s[ty * 4 + i][tx * 6 + jj] = v;
        }
    }
    __syncthreads();
    // route2: (tok, t) pairs, 32 tokens per pass
    #pragma unroll
    for (int half = 0; half < 2; half++) {
        int tok = (tid >> 3) + half * 32;
        int t = tid & 7;
        float s = b2r[t];
        #pragma unroll 8
        for (int j = 0; j < 96; j++) s += hm_s[tok][j] * W2s[t][j];
        lg_s[tok][t] = s;
    }
    __syncthreads();
    if (tid < 64) {
        int tok = tid;
        int l = t0base + tok;
        float mx = -1e30f;
        #pragma unroll
        for (int t = 0; t < NTOK; t++) mx = fmaxf(mx, lg_s[tok][t]);
        float e[NTOK], sum = 0.f;
        #pragma unroll
        for (int t = 0; t < NTOK; t++) { e[t] = expf(lg_s[tok][t] - mx); sum += e[t]; }
        float inv = 1.0f / sum;
        float inten = g_intensity[l];
        float best = -1e30f; int kbest = 0; float rw0 = 0.f;
        #pragma unroll
        for (int t = 0; t < NTOK; t++) {
            float rw = e[t] * inv;
            if (t == 0) rw0 = rw;
            float sim = 1.0f - fabsf(emb[t] - inten);
            float u = gumbel[(size_t)l * NTOK + t];
            u = fmaxf(u, 1e-10f);
            float g = -logf(-logf(u));
            float sc = rw * sim + g;
            if (sc > best) { best = sc; kbest = t; }
        }
        float ek = emb[kbest];
        g_gamma[l] = 0.3f + 0.7f / (1.0f + expf(-ek));
        g_beta[l]  = rw0 - 0.5f;
    }
}

// ---------------- K5: xs = gamma*x+beta, v=D*xs, LayerNorm, out = yn@out_w^T + b --
// 64 tokens per block. yn held in dynamic smem, 192x192 projection tiled with
// 16-wide k chunks of out_w staged in smem. Thread tile: 4 tok x 12 oc.
__global__ __launch_bounds__(256) void k_final(const float* __restrict__ x,
                                               const float* __restrict__ Dv,
                                               const float* __restrict__ ln_w,
                                               const float* __restrict__ ln_b,
                                               const float* __restrict__ out_w,
                                               const float* __restrict__ out_b,
                                               float* __restrict__ out) {
    extern __shared__ float sh[];
    float* v_s  = sh;                 // [64][193]
    float* Bs   = sh + 64 * 193;      // [16][196]
    float* mu_s = Bs + 16 * 196;      // [64]
    float* rs_s = mu_s + 64;          // [64]

    int tid = threadIdx.x;
    int l0 = blockIdx.x * 64;
    int tx = tid & 15;   // oc group: tx*12 + j
    int ty = tid >> 4;   // tok group: ty*4 + i

    for (int idx = tid; idx < 64 * DIM; idx += 256) {
        int tok = idx / DIM, c = idx - tok * DIM;
        int l = l0 + tok;
        float vv = Dv[c] * (g_gamma[l] * x[(size_t)l * DIM + c] + g_beta[l]);
        v_s[tok * 193 + c] = vv;
    }
    __syncthreads();
    if (tid < 64) {
        float s = 0.f, sq = 0.f;
        const float* row = v_s + tid * 193;
        #pragma unroll 8
        for (int c = 0; c < DIM; c++) { float v = row[c]; s += v; sq += v * v; }
        float mu = s * (1.0f / DIM);
        float var = sq * (1.0f / DIM) - mu * mu;
        mu_s[tid] = mu;
        rs_s[tid] = rsqrtf(var + 1e-5f);
    }
    __syncthreads();
    for (int idx = tid; idx < 64 * DIM; idx += 256) {
        int tok = idx / DIM, c = idx - tok * DIM;
        v_s[tok * 193 + c] = (v_s[tok * 193 + c] - mu_s[tok]) * rs_s[tok] * ln_w[c] + ln_b[c];
    }

    float acc[4][12];
    #pragma unroll
    for (int i = 0; i < 4; i++)
        #pragma unroll
        for (int j = 0; j < 12; j++) acc[i][j] = 0.f;

    for (int k0 = 0; k0 < DIM; k0 += 16) {
        __syncthreads();
        for (int idx = tid; idx < 3072; idx += 256) {
            int o = idx >> 4, kk = idx & 15;
            Bs[kk * 196 + o] = out_w[o * DIM + k0 + kk];
        }
        __syncthreads();
        #pragma unroll
        for (int kk = 0; kk < 16; kk++) {
            float a[4];
            #pragma unroll
            for (int i = 0; i < 4; i++) a[i] = v_s[(ty * 4 + i) * 193 + k0 + kk];
            const float4* bp = (const float4*)&Bs[kk * 196 + tx * 12];
            float4 b0 = bp[0], b1 = bp[1], b2 = bp[2];
            float bv[12] = {b0.x, b0.y, b0.z, b0.w, b1.x, b1.y, b1.z, b1.w,
                            b2.x, b2.y, b2.z, b2.w};
            #pragma unroll
            for (int i = 0; i < 4; i++)
                #pragma unroll
                for (int j = 0; j < 12; j++) acc[i][j] += a[i] * bv[j];
        }
    }
    float bb[12];
    #pragma unroll
    for (int j = 0; j < 12; j++) bb[j] = out_b[tx * 12 + j];
    #pragma unroll
    for (int i = 0; i < 4; i++) {
        int l = l0 + ty * 4 + i;
        float* op = out + (size_t)l * DIM + tx * 12;
        #pragma unroll
        for (int q = 0; q < 3; q++) {
            float4 o = make_float4(acc[i][q * 4 + 0] + bb[q * 4 + 0],
                                   acc[i][q * 4 + 1] + bb[q * 4 + 1],
                                   acc[i][q * 4 + 2] + bb[q * 4 + 2],
                                   acc[i][q * 4 + 3] + bb[q * 4 + 3]);
            *(float4*)(op + q * 4) = o;
        }
    }
}

// ---------------- launch ----------------
extern "C" void kernel_launch(void* const* d_in, const int* in_sizes, int n_in,
                              void* d_out, int out_size) {
    const float* x        = (const float*)d_in[0];
    const float* gumbel_u = (const float*)d_in[1];
    const float* conv1_w  = (const float*)d_in[2];
    const float* conv1_b  = (const float*)d_in[3];
    const float* conv2_w  = (const float*)d_in[4];
    const float* conv2_b  = (const float*)d_in[5];
    const float* route1_w = (const float*)d_in[6];
    const float* route1_b = (const float*)d_in[7];
    const float* route2_w = (const float*)d_in[8];
    const float* route2_b = (const float*)d_in[9];
    // d_in[10] A_log, d_in[11] D, d_in[12] ln_w, d_in[13] ln_b
    const float* Dv       = (const float*)d_in[11];
    const float* ln_w     = (const float*)d_in[12];
    const float* ln_b     = (const float*)d_in[13];
    const float* out_w    = (const float*)d_in[14];
    const float* out_b    = (const float*)d_in[15];
    const float* emb      = (const float*)d_in[16];
    float* out = (float*)d_out;

    static int smem_set = 0;
    int k5_smem = (64 * 193 + 16 * 196 + 128) * (int)sizeof(float);
    cudaFuncSetAttribute(k_final, cudaFuncAttributeMaxDynamicSharedMemorySize, k5_smem);
    (void)smem_set;

    k_intensity<<<L_TOT / 256, 256>>>(x);
    k_conv1<<<dim3(L_TOT / 256, C1), 256>>>(conv1_w, conv1_b);
    k_conv2<<<3 * (L_TOT / 64), 256>>>(conv2_w, conv2_b);
    k_route<<<L_TOT / 64, 256>>>(x, route1_w, route1_b, route2_w, route2_b,
                                 gumbel_u, emb);
    k_final<<<L_TOT / 64, 256, k5_smem>>>(x, Dv, ln_w, ln_b, out_w, out_b, out);
}